// round 1
// baseline (speedup 1.0000x reference)
#include <cuda_runtime.h>
#include <math.h>

#define L 96
#define LL2 (L*L)
#define L3 (L*L*L)

typedef unsigned long long ull;

// Scratch (allocation-free rule: __device__ globals)
__device__ float g_bonds[12 * L3];   // planar [c][L3]
__device__ float g_y1[16 * L3];      // planar [c][L3]
__device__ float g_part[3456 * 32];  // per-block channel partial sums (conv2 grid = 3456)

// ---------- packed fp32x2 helpers (sm_10x) ----------
__device__ __forceinline__ ull pack2(float x) {
    ull r; asm("mov.b64 %0, {%1, %1};" : "=l"(r) : "f"(x)); return r;
}
__device__ __forceinline__ void fma2(ull& d, ull a, ull b) {
    asm("fma.rn.f32x2 %0, %1, %2, %0;" : "+l"(d) : "l"(a), "l"(b));
}
__device__ __forceinline__ void unpack2(ull v, float& lo, float& hi) {
    asm("mov.b64 {%0, %1}, %2;" : "=f"(lo), "=f"(hi) : "l"(v));
}
__device__ __forceinline__ float eluf(float x) {
    return x > 0.f ? x : (expf(x) - 1.f);
}
__device__ __forceinline__ int wrapi(int a) {
    return a < 0 ? a + L : (a >= L ? a - L : a);
}

// ---------- Kernel 1: bonds ----------
// v_t = tetraeder_2[x_t] in R^2; all 12 bonds are dot products of rows of the
// 2x2 table, so each bond = d[a][b] with d precomputed per thread.
__global__ void bonds_kernel(const int* __restrict__ lx, const float* __restrict__ tet) {
    int idx = blockIdx.x * blockDim.x + threadIdx.x;
    if (idx >= L3) return;
    int z = idx % L;
    int y = (idx / L) % L;
    int x = idx / LL2;

    float t00 = tet[0], t01 = tet[1], t10 = tet[2], t11 = tet[3];
    float d00 = t00 * t00 + t01 * t01;
    float d01 = t00 * t10 + t01 * t11;
    float d11 = t10 * t10 + t11 * t11;
    float dt[4] = {d00, d01, d01, d11};

    int4 a = *(const int4*)&lx[idx * 4];
    int a0 = a.x, a1 = a.y, a2 = a.z, a3 = a.w;

    int xm = x ? x - 1 : L - 1;
    int ym = y ? y - 1 : L - 1;
    int zm = z ? z - 1 : L - 1;
    // roll(v,1,axis) => value at (coord-1)
    int b1 = lx[((xm * L + y) * L + z) * 4 + 1];
    int b2 = lx[((x * L + ym) * L + z) * 4 + 2];
    int b3 = lx[((x * L + y) * L + zm) * 4 + 3];

    g_bonds[0 * L3 + idx]  = dt[a0 * 2 + a1];
    g_bonds[1 * L3 + idx]  = dt[a0 * 2 + a2];
    g_bonds[2 * L3 + idx]  = dt[a0 * 2 + a3];
    g_bonds[3 * L3 + idx]  = dt[a0 * 2 + b1];
    g_bonds[4 * L3 + idx]  = dt[a0 * 2 + b2];
    g_bonds[5 * L3 + idx]  = dt[a0 * 2 + b3];
    g_bonds[6 * L3 + idx]  = dt[a1 * 2 + a2];
    g_bonds[7 * L3 + idx]  = dt[a2 * 2 + a3];
    g_bonds[8 * L3 + idx]  = dt[a3 * 2 + a1];
    g_bonds[9 * L3 + idx]  = dt[b1 * 2 + b2];
    g_bonds[10 * L3 + idx] = dt[b2 * 2 + b3];
    g_bonds[11 * L3 + idx] = dt[b3 * 2 + b1];
}

// ---------- Kernel 2: conv1 (12->16) + ELU ----------
// 1 thread = 4 consecutive z sites, 16 couts as 8 packed f32x2 accumulators.
// grid = 96*96*24 threads / 128 = 1728 blocks.
__global__ __launch_bounds__(128) void conv1_kernel(const float* __restrict__ w1,
                                                    const float* __restrict__ b1) {
    __shared__ float sw[27 * 12 * 16];
    for (int i = threadIdx.x; i < 27 * 12 * 16; i += 128) sw[i] = w1[i];
    __syncthreads();

    int gid = blockIdx.x * 128 + threadIdx.x;
    int zg = gid % 24;
    int rest = gid / 24;
    int y = rest % L;
    int x = rest / L;
    int z0 = zg * 4;

    int zoff[6];
#pragma unroll
    for (int j = 0; j < 6; j++) zoff[j] = wrapi(z0 - 1 + j);

    ull acc[4][8];
    const ull* bb = (const ull*)b1;
#pragma unroll
    for (int p = 0; p < 8; p++) {
        ull bv = bb[p];
        acc[0][p] = bv; acc[1][p] = bv; acc[2][p] = bv; acc[3][p] = bv;
    }

    for (int kd = 0; kd < 3; kd++) {
        int xn = wrapi(x + kd - 1);
        for (int kh = 0; kh < 3; kh++) {
            int yn = wrapi(y + kh - 1);
            int rowbase = (xn * L + yn) * L;
            const float* wb = &sw[(kd * 3 + kh) * 3 * 12 * 16];
            for (int ci = 0; ci < 12; ci++) {
                const float* bp = &g_bonds[ci * L3 + rowbase];
                ull pv[6];
#pragma unroll
                for (int j = 0; j < 6; j++) pv[j] = pack2(__ldg(bp + zoff[j]));
#pragma unroll
                for (int kw = 0; kw < 3; kw++) {
                    const ull* wp = (const ull*)&wb[(kw * 12 + ci) * 16];
#pragma unroll
                    for (int p = 0; p < 8; p++) {
                        ull w = wp[p];  // broadcast LDS.64
                        fma2(acc[0][p], pv[0 + kw], w);
                        fma2(acc[1][p], pv[1 + kw], w);
                        fma2(acc[2][p], pv[2 + kw], w);
                        fma2(acc[3][p], pv[3 + kw], w);
                    }
                }
            }
        }
    }

    int base = (x * L + y) * L + z0;
#pragma unroll
    for (int p = 0; p < 8; p++) {
        float l0, h0, l1, h1, l2, h2, l3, h3;
        unpack2(acc[0][p], l0, h0);
        unpack2(acc[1][p], l1, h1);
        unpack2(acc[2][p], l2, h2);
        unpack2(acc[3][p], l3, h3);
        float4 qe = make_float4(eluf(l0), eluf(l1), eluf(l2), eluf(l3));
        float4 qo = make_float4(eluf(h0), eluf(h1), eluf(h2), eluf(h3));
        *(float4*)&g_y1[(2 * p) * L3 + base] = qe;      // cout 2p
        *(float4*)&g_y1[(2 * p + 1) * L3 + base] = qo;  // cout 2p+1
    }
}

// ---------- Kernel 3: conv2 (16->32) + ELU + block reduction ----------
// 1 thread = 2 consecutive z sites, 32 couts as 16 packed f32x2 accumulators.
// Weights staged per-kd slice (18 KB) to stay in static smem.
// grid = 96*96*48 threads / 128 = 3456 blocks.
__global__ __launch_bounds__(128) void conv2_kernel(const float* __restrict__ w2,
                                                    const float* __restrict__ b2) {
    __shared__ float sw[9 * 16 * 32];
    __shared__ float red[4][32];

    int gid = blockIdx.x * 128 + threadIdx.x;
    int zg = gid % 48;
    int rest = gid / 48;
    int y = rest % L;
    int x = rest / L;
    int z0 = zg * 2;

    int zoff[4];
#pragma unroll
    for (int j = 0; j < 4; j++) zoff[j] = wrapi(z0 - 1 + j);

    ull acc[2][16];
    const ull* bb = (const ull*)b2;
#pragma unroll
    for (int p = 0; p < 16; p++) { acc[0][p] = bb[p]; acc[1][p] = bb[p]; }

    for (int kd = 0; kd < 3; kd++) {
        __syncthreads();
        for (int i = threadIdx.x; i < 9 * 16 * 32; i += 128)
            sw[i] = w2[kd * 9 * 16 * 32 + i];
        __syncthreads();

        int xn = wrapi(x + kd - 1);
        for (int kh = 0; kh < 3; kh++) {
            int yn = wrapi(y + kh - 1);
            int rowbase = (xn * L + yn) * L;
            const float* wb = &sw[kh * 3 * 16 * 32];
            for (int ci = 0; ci < 16; ci++) {
                const float* bp = &g_y1[ci * L3 + rowbase];
                ull pv[4];
#pragma unroll
                for (int j = 0; j < 4; j++) pv[j] = pack2(__ldg(bp + zoff[j]));
#pragma unroll
                for (int kw = 0; kw < 3; kw++) {
                    const ull* wp = (const ull*)&wb[(kw * 16 + ci) * 32];
#pragma unroll
                    for (int p = 0; p < 16; p++) {
                        ull w = wp[p];
                        fma2(acc[0][p], pv[kw], w);
                        fma2(acc[1][p], pv[1 + kw], w);
                    }
                }
            }
        }
    }

    // ELU + per-thread channel sums over the 2 sites
    float s[32];
#pragma unroll
    for (int p = 0; p < 16; p++) {
        float l0, h0, l1, h1;
        unpack2(acc[0][p], l0, h0);
        unpack2(acc[1][p], l1, h1);
        s[2 * p]     = eluf(l0) + eluf(l1);
        s[2 * p + 1] = eluf(h0) + eluf(h1);
    }
    // deterministic warp butterfly reduction (all lanes end with warp sums)
#pragma unroll
    for (int off = 16; off; off >>= 1)
#pragma unroll
        for (int c = 0; c < 32; c++)
            s[c] += __shfl_xor_sync(0xffffffffu, s[c], off);

    int lane = threadIdx.x & 31, wrp = threadIdx.x >> 5;
    red[wrp][lane] = s[lane];  // lane l carries channel l's warp sum
    __syncthreads();
    if (threadIdx.x < 32) {
        int c = threadIdx.x;
        g_part[blockIdx.x * 32 + c] =
            red[0][c] + red[1][c] + red[2][c] + red[3][c];
    }
}

// ---------- Kernel 4: deterministic final reduce + mean + dot ----------
__global__ void final_kernel(const float* __restrict__ wd, float* __restrict__ out) {
    __shared__ float sm[256];
    int t = threadIdx.x;          // 256 threads
    int ch = t & 31, grp = t >> 5;  // 8 groups of 32 channels
    float s = 0.f;
    for (int b = grp; b < 3456; b += 8) s += g_part[b * 32 + ch];
    sm[t] = s;
    __syncthreads();
    if (t < 32) {
        float v = 0.f;
#pragma unroll
        for (int g = 0; g < 8; g++) v += sm[g * 32 + t];
        v = (v / (float)L3) * wd[t];
#pragma unroll
        for (int off = 16; off; off >>= 1)
            v += __shfl_xor_sync(0xffffffffu, v, off);
        if (t == 0) out[0] = v;
    }
}

extern "C" void kernel_launch(void* const* d_in, const int* in_sizes, int n_in,
                              void* d_out, int out_size) {
    (void)in_sizes; (void)n_in; (void)out_size;
    const int*   lx  = (const int*)d_in[0];
    const float* tet = (const float*)d_in[1];
    const float* w1  = (const float*)d_in[2];
    const float* b1  = (const float*)d_in[3];
    const float* w2  = (const float*)d_in[4];
    const float* b2  = (const float*)d_in[5];
    const float* wd  = (const float*)d_in[6];

    bonds_kernel<<<3456, 256>>>(lx, tet);
    conv1_kernel<<<1728, 128>>>(w1, b1);
    conv2_kernel<<<3456, 128>>>(w2, b2);
    final_kernel<<<1, 256>>>(wd, (float*)d_out);
}

// round 2
// speedup vs baseline: 1.0006x; 1.0006x over previous
#include <cuda_runtime.h>
#include <math.h>

#define L 96
#define LL2 (L*L)
#define L3 (L*L*L)

typedef unsigned long long ull;

// Scratch (allocation-free rule: __device__ globals)
__device__ float g_bonds[12 * L3];   // planar [c][L3]
__device__ float g_y1[16 * L3];      // planar [c][L3]
__device__ float g_part[3456 * 32];  // per-block channel partial sums (conv2 grid = 3456)

// ---------- packed fp32x2 helpers (sm_10x) ----------
__device__ __forceinline__ ull pack2(float x) {
    ull r; asm("mov.b64 %0, {%1, %1};" : "=l"(r) : "f"(x)); return r;
}
__device__ __forceinline__ void fma2(ull& d, ull a, ull b) {
    asm("fma.rn.f32x2 %0, %1, %2, %0;" : "+l"(d) : "l"(a), "l"(b));
}
__device__ __forceinline__ void unpack2(ull v, float& lo, float& hi) {
    asm("mov.b64 {%0, %1}, %2;" : "=f"(lo), "=f"(hi) : "l"(v));
}
__device__ __forceinline__ float eluf(float x) {
    return x > 0.f ? x : (expf(x) - 1.f);
}
__device__ __forceinline__ int wrapi(int a) {
    return a < 0 ? a + L : (a >= L ? a - L : a);
}

// ---------- Kernel 1: bonds ----------
// v_t = tetraeder_2[x_t] in R^2; all 12 bonds are dot products of rows of the
// 2x2 table, so each bond = d[a][b] with d precomputed per thread.
__global__ void bonds_kernel(const int* __restrict__ lx, const float* __restrict__ tet) {
    int idx = blockIdx.x * blockDim.x + threadIdx.x;
    if (idx >= L3) return;
    int z = idx % L;
    int y = (idx / L) % L;
    int x = idx / LL2;

    float t00 = tet[0], t01 = tet[1], t10 = tet[2], t11 = tet[3];
    float d00 = t00 * t00 + t01 * t01;
    float d01 = t00 * t10 + t01 * t11;
    float d11 = t10 * t10 + t11 * t11;
    float dt[4] = {d00, d01, d01, d11};

    int4 a = *(const int4*)&lx[idx * 4];
    int a0 = a.x, a1 = a.y, a2 = a.z, a3 = a.w;

    int xm = x ? x - 1 : L - 1;
    int ym = y ? y - 1 : L - 1;
    int zm = z ? z - 1 : L - 1;
    // roll(v,1,axis) => value at (coord-1)
    int b1 = lx[((xm * L + y) * L + z) * 4 + 1];
    int b2 = lx[((x * L + ym) * L + z) * 4 + 2];
    int b3 = lx[((x * L + y) * L + zm) * 4 + 3];

    g_bonds[0 * L3 + idx]  = dt[a0 * 2 + a1];
    g_bonds[1 * L3 + idx]  = dt[a0 * 2 + a2];
    g_bonds[2 * L3 + idx]  = dt[a0 * 2 + a3];
    g_bonds[3 * L3 + idx]  = dt[a0 * 2 + b1];
    g_bonds[4 * L3 + idx]  = dt[a0 * 2 + b2];
    g_bonds[5 * L3 + idx]  = dt[a0 * 2 + b3];
    g_bonds[6 * L3 + idx]  = dt[a1 * 2 + a2];
    g_bonds[7 * L3 + idx]  = dt[a2 * 2 + a3];
    g_bonds[8 * L3 + idx]  = dt[a3 * 2 + a1];
    g_bonds[9 * L3 + idx]  = dt[b1 * 2 + b2];
    g_bonds[10 * L3 + idx] = dt[b2 * 2 + b3];
    g_bonds[11 * L3 + idx] = dt[b3 * 2 + b1];
}

// ---------- Kernel 2: conv1 (12->16) + ELU ----------
// 1 thread = 4 consecutive z sites, 16 couts as 8 packed f32x2 accumulators.
// grid = 96*96*24 threads / 128 = 1728 blocks.
__global__ __launch_bounds__(128) void conv1_kernel(const float* __restrict__ w1,
                                                    const float* __restrict__ b1) {
    __shared__ float sw[27 * 12 * 16];
    for (int i = threadIdx.x; i < 27 * 12 * 16; i += 128) sw[i] = w1[i];
    __syncthreads();

    int gid = blockIdx.x * 128 + threadIdx.x;
    int zg = gid % 24;
    int rest = gid / 24;
    int y = rest % L;
    int x = rest / L;
    int z0 = zg * 4;

    int zoff[6];
#pragma unroll
    for (int j = 0; j < 6; j++) zoff[j] = wrapi(z0 - 1 + j);

    ull acc[4][8];
    const ull* bb = (const ull*)b1;
#pragma unroll
    for (int p = 0; p < 8; p++) {
        ull bv = bb[p];
        acc[0][p] = bv; acc[1][p] = bv; acc[2][p] = bv; acc[3][p] = bv;
    }

    for (int kd = 0; kd < 3; kd++) {
        int xn = wrapi(x + kd - 1);
        for (int kh = 0; kh < 3; kh++) {
            int yn = wrapi(y + kh - 1);
            int rowbase = (xn * L + yn) * L;
            const float* wb = &sw[(kd * 3 + kh) * 3 * 12 * 16];
            for (int ci = 0; ci < 12; ci++) {
                const float* bp = &g_bonds[ci * L3 + rowbase];
                ull pv[6];
#pragma unroll
                for (int j = 0; j < 6; j++) pv[j] = pack2(__ldg(bp + zoff[j]));
#pragma unroll
                for (int kw = 0; kw < 3; kw++) {
                    const ull* wp = (const ull*)&wb[(kw * 12 + ci) * 16];
#pragma unroll
                    for (int p = 0; p < 8; p++) {
                        ull w = wp[p];  // broadcast LDS.64
                        fma2(acc[0][p], pv[0 + kw], w);
                        fma2(acc[1][p], pv[1 + kw], w);
                        fma2(acc[2][p], pv[2 + kw], w);
                        fma2(acc[3][p], pv[3 + kw], w);
                    }
                }
            }
        }
    }

    int base = (x * L + y) * L + z0;
#pragma unroll
    for (int p = 0; p < 8; p++) {
        float l0, h0, l1, h1, l2, h2, l3, h3;
        unpack2(acc[0][p], l0, h0);
        unpack2(acc[1][p], l1, h1);
        unpack2(acc[2][p], l2, h2);
        unpack2(acc[3][p], l3, h3);
        float4 qe = make_float4(eluf(l0), eluf(l1), eluf(l2), eluf(l3));
        float4 qo = make_float4(eluf(h0), eluf(h1), eluf(h2), eluf(h3));
        *(float4*)&g_y1[(2 * p) * L3 + base] = qe;      // cout 2p
        *(float4*)&g_y1[(2 * p + 1) * L3 + base] = qo;  // cout 2p+1
    }
}

// ---------- Kernel 3: conv2 (16->32) + ELU + block reduction ----------
// 1 thread = 2 consecutive z sites, 32 couts as 16 packed f32x2 accumulators.
// Weights staged per-kd slice (18 KB) to stay in static smem.
// grid = 96*96*48 threads / 128 = 3456 blocks.
__global__ __launch_bounds__(128) void conv2_kernel(const float* __restrict__ w2,
                                                    const float* __restrict__ b2) {
    __shared__ float sw[9 * 16 * 32];
    __shared__ float red[4][32];

    int gid = blockIdx.x * 128 + threadIdx.x;
    int zg = gid % 48;
    int rest = gid / 48;
    int y = rest % L;
    int x = rest / L;
    int z0 = zg * 2;

    int zoff[4];
#pragma unroll
    for (int j = 0; j < 4; j++) zoff[j] = wrapi(z0 - 1 + j);

    ull acc[2][16];
    const ull* bb = (const ull*)b2;
#pragma unroll
    for (int p = 0; p < 16; p++) { acc[0][p] = bb[p]; acc[1][p] = bb[p]; }

    for (int kd = 0; kd < 3; kd++) {
        __syncthreads();
        for (int i = threadIdx.x; i < 9 * 16 * 32; i += 128)
            sw[i] = w2[kd * 9 * 16 * 32 + i];
        __syncthreads();

        int xn = wrapi(x + kd - 1);
        for (int kh = 0; kh < 3; kh++) {
            int yn = wrapi(y + kh - 1);
            int rowbase = (xn * L + yn) * L;
            const float* wb = &sw[kh * 3 * 16 * 32];
            for (int ci = 0; ci < 16; ci++) {
                const float* bp = &g_y1[ci * L3 + rowbase];
                ull pv[4];
#pragma unroll
                for (int j = 0; j < 4; j++) pv[j] = pack2(__ldg(bp + zoff[j]));
#pragma unroll
                for (int kw = 0; kw < 3; kw++) {
                    const ull* wp = (const ull*)&wb[(kw * 16 + ci) * 32];
#pragma unroll
                    for (int p = 0; p < 16; p++) {
                        ull w = wp[p];
                        fma2(acc[0][p], pv[kw], w);
                        fma2(acc[1][p], pv[1 + kw], w);
                    }
                }
            }
        }
    }

    // ELU + per-thread channel sums over the 2 sites
    float s[32];
#pragma unroll
    for (int p = 0; p < 16; p++) {
        float l0, h0, l1, h1;
        unpack2(acc[0][p], l0, h0);
        unpack2(acc[1][p], l1, h1);
        s[2 * p]     = eluf(l0) + eluf(l1);
        s[2 * p + 1] = eluf(h0) + eluf(h1);
    }
    // deterministic warp butterfly reduction (all lanes end with warp sums)
#pragma unroll
    for (int off = 16; off; off >>= 1)
#pragma unroll
        for (int c = 0; c < 32; c++)
            s[c] += __shfl_xor_sync(0xffffffffu, s[c], off);

    int lane = threadIdx.x & 31, wrp = threadIdx.x >> 5;
    red[wrp][lane] = s[lane];  // lane l carries channel l's warp sum
    __syncthreads();
    if (threadIdx.x < 32) {
        int c = threadIdx.x;
        g_part[blockIdx.x * 32 + c] =
            red[0][c] + red[1][c] + red[2][c] + red[3][c];
    }
}

// ---------- Kernel 4: deterministic final reduce + mean + dot ----------
__global__ void final_kernel(const float* __restrict__ wd, float* __restrict__ out) {
    __shared__ float sm[256];
    int t = threadIdx.x;          // 256 threads
    int ch = t & 31, grp = t >> 5;  // 8 groups of 32 channels
    float s = 0.f;
    for (int b = grp; b < 3456; b += 8) s += g_part[b * 32 + ch];
    sm[t] = s;
    __syncthreads();
    if (t < 32) {
        float v = 0.f;
#pragma unroll
        for (int g = 0; g < 8; g++) v += sm[g * 32 + t];
        v = (v / (float)L3) * wd[t];
#pragma unroll
        for (int off = 16; off; off >>= 1)
            v += __shfl_xor_sync(0xffffffffu, v, off);
        if (t == 0) out[0] = v;
    }
}

extern "C" void kernel_launch(void* const* d_in, const int* in_sizes, int n_in,
                              void* d_out, int out_size) {
    (void)in_sizes; (void)n_in; (void)out_size;
    const int*   lx  = (const int*)d_in[0];
    const float* tet = (const float*)d_in[1];
    const float* w1  = (const float*)d_in[2];
    const float* b1  = (const float*)d_in[3];
    const float* w2  = (const float*)d_in[4];
    const float* b2  = (const float*)d_in[5];
    const float* wd  = (const float*)d_in[6];

    bonds_kernel<<<3456, 256>>>(lx, tet);
    conv1_kernel<<<1728, 128>>>(w1, b1);
    conv2_kernel<<<3456, 128>>>(w2, b2);
    final_kernel<<<1, 256>>>(wd, (float*)d_out);
}

// round 4
// speedup vs baseline: 1.7221x; 1.7210x over previous
#include <cuda_runtime.h>
#include <cuda_bf16.h>
#include <stdint.h>
#include <math.h>

#define L 96
#define LL2 (L*L)
#define L3 (L*L*L)

typedef unsigned long long ull;

// ---------------- device scratch (allocation-free rule) ----------------
// Packed input layout: per site, 8 u64 words; word c = channels (2c,2c+1):
//   bits[ 0:32) = {bf16 hi(2c) | bf16 hi(2c+1)<<16}
//   bits[32:64) = {bf16 lo(2c) | bf16 lo(2c+1)<<16}
__device__ __align__(16) ull g_bp[L3 * 8];    // bonds (12 ch + 4 zero pad)
__device__ __align__(16) ull g_y1p[L3 * 8];   // conv1 output (16 ch)
// Pre-built mma.sync B fragments: [tap][ntile][reg][lane], hi|lo packed
__device__ __align__(16) ull g_Bf1[27 * 2 * 2 * 32];
__device__ __align__(16) ull g_Bf2[27 * 4 * 2 * 32];
__device__ float g_part[432 * 32];

// ---------------- helpers ----------------
__device__ __forceinline__ int wrapi(int a) {
    return a < 0 ? a + L : (a >= L ? a - L : a);
}
__device__ __forceinline__ float eluf(float x) {
    return x > 0.f ? x : expm1f(x);
}
// pack two floats into {hi pair | lo pair} u64
__device__ __forceinline__ ull pack2ch(float v0, float v1) {
    __nv_bfloat16 h0 = __float2bfloat16(v0);
    __nv_bfloat16 h1 = __float2bfloat16(v1);
    __nv_bfloat16 l0 = __float2bfloat16(v0 - __bfloat162float(h0));
    __nv_bfloat16 l1 = __float2bfloat16(v1 - __bfloat162float(h1));
    uint32_t hu = (uint32_t)__bfloat16_as_ushort(h0) |
                  ((uint32_t)__bfloat16_as_ushort(h1) << 16);
    uint32_t lu = (uint32_t)__bfloat16_as_ushort(l0) |
                  ((uint32_t)__bfloat16_as_ushort(l1) << 16);
    return (ull)hu | ((ull)lu << 32);
}

#define MMA_BF16(D, A, B0, B1)                                              \
    asm("mma.sync.aligned.m16n8k16.row.col.f32.bf16.bf16.f32 "              \
        "{%0,%1,%2,%3}, {%4,%5,%6,%7}, {%8,%9}, {%0,%1,%2,%3};"             \
        : "+f"((D)[0]), "+f"((D)[1]), "+f"((D)[2]), "+f"((D)[3])            \
        : "r"((A)[0]), "r"((A)[1]), "r"((A)[2]), "r"((A)[3]),               \
          "r"(B0), "r"(B1))

// ---------------- Kernel 1: bonds -> packed hi/lo ----------------
__global__ __launch_bounds__(256) void bonds_kernel(const int* __restrict__ lx,
                                                    const float* __restrict__ tet) {
    int idx = blockIdx.x * 256 + threadIdx.x;
    if (idx >= L3) return;
    int z = idx % L;
    int y = (idx / L) % L;
    int x = idx / LL2;

    float t00 = tet[0], t01 = tet[1], t10 = tet[2], t11 = tet[3];
    float d00 = t00 * t00 + t01 * t01;
    float d01 = t00 * t10 + t01 * t11;
    float d11 = t10 * t10 + t11 * t11;
    float dt[4] = {d00, d01, d01, d11};

    int4 a = *(const int4*)&lx[idx * 4];
    int a0 = a.x, a1 = a.y, a2 = a.z, a3 = a.w;
    int xm = x ? x - 1 : L - 1;
    int ym = y ? y - 1 : L - 1;
    int zm = z ? z - 1 : L - 1;
    int b1 = lx[((xm * L + y) * L + z) * 4 + 1];
    int b2 = lx[((x * L + ym) * L + z) * 4 + 2];
    int b3 = lx[((x * L + y) * L + zm) * 4 + 3];

    float v[12];
    v[0] = dt[a0 * 2 + a1];  v[1] = dt[a0 * 2 + a2];  v[2]  = dt[a0 * 2 + a3];
    v[3] = dt[a0 * 2 + b1];  v[4] = dt[a0 * 2 + b2];  v[5]  = dt[a0 * 2 + b3];
    v[6] = dt[a1 * 2 + a2];  v[7] = dt[a2 * 2 + a3];  v[8]  = dt[a3 * 2 + a1];
    v[9] = dt[b1 * 2 + b2];  v[10] = dt[b2 * 2 + b3]; v[11] = dt[b3 * 2 + b1];

    ull* dst = &g_bp[(size_t)idx * 8];
#pragma unroll
    for (int c = 0; c < 6; c++) dst[c] = pack2ch(v[2 * c], v[2 * c + 1]);
    dst[6] = 0ull;
    dst[7] = 0ull;
}

// ---------------- Kernel 2: weight -> B-fragment prep ----------------
__global__ __launch_bounds__(256) void prep_kernel(const float* __restrict__ w1,
                                                   const float* __restrict__ w2) {
    int i = blockIdx.x * 256 + threadIdx.x;
    if (i < 27 * 2 * 2 * 32) {  // conv1 frags
        int lane = i & 31, reg = (i >> 5) & 1, nt = (i >> 6) & 1, tap = i >> 7;
        int t = lane & 3;
        int n = nt * 8 + (lane >> 2);
        int k0 = t * 2 + reg * 8;
        float v0 = (k0 < 12)     ? w1[(tap * 12 + k0) * 16 + n]     : 0.f;
        float v1 = (k0 + 1 < 12) ? w1[(tap * 12 + k0 + 1) * 16 + n] : 0.f;
        g_Bf1[i] = pack2ch(v0, v1);
    }
    int j = i - 27 * 2 * 2 * 32;
    if (j >= 0 && j < 27 * 4 * 2 * 32) {  // conv2 frags
        int lane = j & 31, reg = (j >> 5) & 1, nt = (j >> 6) & 3, tap = j >> 8;
        int t = lane & 3;
        int n = nt * 8 + (lane >> 2);
        int k0 = t * 2 + reg * 8;
        float v0 = w2[(tap * 16 + k0) * 32 + n];
        float v1 = w2[(tap * 16 + k0 + 1) * 32 + n];
        g_Bf2[j] = pack2ch(v0, v1);
    }
}

// ---------------- conv kernels: mma.sync, 3-term bf16 split ----------------
// Warp tile = 32 z-consecutive sites (two m16 tiles). 8 warps/CTA, 8 tiles/warp.
// 27648 warp-tiles total = 432 CTAs * 8 warps * 8 tiles.
template <int NT, bool FIRST>
__global__ __launch_bounds__(256) void conv_kernel(const float* __restrict__ bias) {
    extern __shared__ ull sB[];
    __shared__ float red[8][32];

    const int tid = threadIdx.x;
    const int wid = tid >> 5, lane = tid & 31;
    const int t = lane & 3, r = lane >> 2;

    // stage B fragments into smem
    const ull* Bsrc = FIRST ? g_Bf1 : g_Bf2;
    const int nB = 27 * NT * 2 * 32;
    for (int i = tid; i < nB; i += 256) sB[i] = __ldg(Bsrc + i);
    __syncthreads();

    const ull* Ain = FIRST ? g_bp : g_y1p;
    const int wg = blockIdx.x * 8 + wid;

    float psum[NT][2];
#pragma unroll
    for (int nt = 0; nt < NT; nt++) { psum[nt][0] = 0.f; psum[nt][1] = 0.f; }

    for (int it = 0; it < 8; it++) {
        int tile = wg * 8 + it;
        int tz = tile % 3;
        int ty = (tile / 3) % L;
        int tx = tile / (3 * L);
        int z0 = tz * 32;

        // wrapped z per kw per row-slot (rows r, r+8, r+16, r+24)
        int zn[3][4];
#pragma unroll
        for (int jj = 0; jj < 4; jj++) {
            int zz = z0 + r + jj * 8;
            zn[0][jj] = wrapi(zz - 1);
            zn[1][jj] = zz;
            zn[2][jj] = wrapi(zz + 1);
        }

        float d[2][NT][4];
#pragma unroll
        for (int nt = 0; nt < NT; nt++) {
            int c0 = nt * 8 + t * 2;
            float b0 = __ldg(bias + c0), b1 = __ldg(bias + c0 + 1);
            d[0][nt][0] = b0; d[0][nt][1] = b1; d[0][nt][2] = b0; d[0][nt][3] = b1;
            d[1][nt][0] = b0; d[1][nt][1] = b1; d[1][nt][2] = b0; d[1][nt][3] = b1;
        }

        for (int kd = 0; kd < 3; kd++) {
            int xn = wrapi(tx + kd - 1);
            for (int kh = 0; kh < 3; kh++) {
                int yn = wrapi(ty + kh - 1);
                const ull* rowp = Ain + (size_t)((xn * L + yn) * L) * 8 + t;
#pragma unroll
                for (int kw = 0; kw < 3; kw++) {
                    const int tap = (kd * 3 + kh) * 3 + kw;
                    uint32_t ahi[2][4], alo[2][4];
#pragma unroll
                    for (int mt = 0; mt < 2; mt++) {
                        int za = zn[kw][mt * 2], zb = zn[kw][mt * 2 + 1];
                        ull q0 = __ldg(rowp + za * 8);
                        ull q1 = __ldg(rowp + zb * 8);
                        ull q2 = __ldg(rowp + za * 8 + 4);
                        ull q3 = __ldg(rowp + zb * 8 + 4);
                        ahi[mt][0] = (uint32_t)q0; alo[mt][0] = (uint32_t)(q0 >> 32);
                        ahi[mt][1] = (uint32_t)q1; alo[mt][1] = (uint32_t)(q1 >> 32);
                        ahi[mt][2] = (uint32_t)q2; alo[mt][2] = (uint32_t)(q2 >> 32);
                        ahi[mt][3] = (uint32_t)q3; alo[mt][3] = (uint32_t)(q3 >> 32);
                    }
                    const ull* bp = &sB[(size_t)tap * NT * 2 * 32 + lane];
#pragma unroll
                    for (int nt = 0; nt < NT; nt++) {
                        ull wq0 = bp[(nt * 2 + 0) * 32];
                        ull wq1 = bp[(nt * 2 + 1) * 32];
                        uint32_t bh0 = (uint32_t)wq0, bh1 = (uint32_t)wq1;
                        uint32_t bl0 = (uint32_t)(wq0 >> 32), bl1 = (uint32_t)(wq1 >> 32);
#pragma unroll
                        for (int mt = 0; mt < 2; mt++) {
                            MMA_BF16(d[mt][nt], ahi[mt], bh0, bh1);
                            MMA_BF16(d[mt][nt], ahi[mt], bl0, bl1);
                            MMA_BF16(d[mt][nt], alo[mt], bh0, bh1);
                        }
                    }
                }
            }
        }

        if (FIRST) {
            // ELU -> packed hi/lo store (channel-last words)
            int sbase = (tx * L + ty) * L + z0;
#pragma unroll
            for (int mt = 0; mt < 2; mt++) {
                int site = sbase + mt * 16 + r;
#pragma unroll
                for (int nt = 0; nt < NT; nt++) {
                    int word = nt * 4 + t;
                    g_y1p[(size_t)site * 8 + word] =
                        pack2ch(eluf(d[mt][nt][0]), eluf(d[mt][nt][1]));
                    g_y1p[(size_t)(site + 8) * 8 + word] =
                        pack2ch(eluf(d[mt][nt][2]), eluf(d[mt][nt][3]));
                }
            }
        } else {
#pragma unroll
            for (int nt = 0; nt < NT; nt++) {
                psum[nt][0] += eluf(d[0][nt][0]) + eluf(d[0][nt][2]) +
                               eluf(d[1][nt][0]) + eluf(d[1][nt][2]);
                psum[nt][1] += eluf(d[0][nt][1]) + eluf(d[0][nt][3]) +
                               eluf(d[1][nt][1]) + eluf(d[1][nt][3]);
            }
        }
    }

    if (!FIRST) {
        // reduce over row-slots (lanes differing in bits 2..4), deterministic
#pragma unroll
        for (int off = 4; off <= 16; off <<= 1)
#pragma unroll
            for (int nt = 0; nt < NT; nt++) {
                psum[nt][0] += __shfl_xor_sync(0xffffffffu, psum[nt][0], off);
                psum[nt][1] += __shfl_xor_sync(0xffffffffu, psum[nt][1], off);
            }
        if (r == 0) {  // lanes 0..3
#pragma unroll
            for (int nt = 0; nt < NT; nt++) {
                red[wid][nt * 8 + t * 2] = psum[nt][0];
                red[wid][nt * 8 + t * 2 + 1] = psum[nt][1];
            }
        }
        __syncthreads();
        if (tid < 32) {
            float s = 0.f;
#pragma unroll
            for (int w = 0; w < 8; w++) s += red[w][tid];
            g_part[blockIdx.x * 32 + tid] = s;
        }
    }
}

// ---------------- final reduction (deterministic) ----------------
__global__ __launch_bounds__(256) void final_kernel(const float* __restrict__ wd,
                                                    float* __restrict__ out) {
    __shared__ float sm[256];
    int tt = threadIdx.x, ch = tt & 31, grp = tt >> 5;
    float s = 0.f;
    for (int b = grp; b < 432; b += 8) s += g_part[b * 32 + ch];
    sm[tt] = s;
    __syncthreads();
    if (tt < 32) {
        float v = 0.f;
#pragma unroll
        for (int g = 0; g < 8; g++) v += sm[g * 32 + tt];
        v = (v / (float)L3) * __ldg(wd + tt);
#pragma unroll
        for (int off = 16; off; off >>= 1)
            v += __shfl_xor_sync(0xffffffffu, v, off);
        if (tt == 0) out[0] = v;
    }
}

// ---------------- launch ----------------
extern "C" void kernel_launch(void* const* d_in, const int* in_sizes, int n_in,
                              void* d_out, int out_size) {
    (void)in_sizes; (void)n_in; (void)out_size;
    const int*   lx  = (const int*)d_in[0];
    const float* tet = (const float*)d_in[1];
    const float* w1  = (const float*)d_in[2];
    const float* b1  = (const float*)d_in[3];
    const float* w2  = (const float*)d_in[4];
    const float* b2  = (const float*)d_in[5];
    const float* wd  = (const float*)d_in[6];

    const int SMEM1 = 27 * 2 * 2 * 32 * 8;  // 27648 B
    const int SMEM2 = 27 * 4 * 2 * 32 * 8;  // 55296 B
    cudaFuncSetAttribute(conv_kernel<2, true>,
                         cudaFuncAttributeMaxDynamicSharedMemorySize, SMEM1);
    cudaFuncSetAttribute(conv_kernel<4, false>,
                         cudaFuncAttributeMaxDynamicSharedMemorySize, SMEM2);

    bonds_kernel<<<3456, 256>>>(lx, tet);
    prep_kernel<<<41, 256>>>(w1, w2);
    conv_kernel<2, true><<<432, 256, SMEM1>>>(b1);
    conv_kernel<4, false><<<432, 256, SMEM2>>>(b2);
    final_kernel<<<1, 256>>>(wd, (float*)d_out);
}

// round 5
// speedup vs baseline: 1.7628x; 1.0237x over previous
#include <cuda_runtime.h>
#include <cuda_bf16.h>
#include <stdint.h>
#include <math.h>

#define L 96
#define LL2 (L*L)
#define L3 (L*L*L)
#define ZP 98                 // z dim with halo: zp=0 <-> z=95, zp=1..96 <-> z=0..95, zp=97 <-> z=0
#define ROWW (ZP*8)           // u64 words per (x,y) row

typedef unsigned long long ull;

// ---------------- device scratch (allocation-free rule) ----------------
// Packed layout: per site, 8 u64 words; word c = channels (2c,2c+1):
//   bits[0:32) = {bf16 hi(2c) | hi(2c+1)<<16}, bits[32:64) = lo pair.
__device__ __align__(16) ull g_bp[L * L * ZP * 8];    // bonds (12 ch + 4 pad)
__device__ __align__(16) ull g_y1p[L * L * ZP * 8];   // conv1 out (16 ch)
// Pre-built mma.sync B fragments: [tap][ntile][reg][lane], hi|lo packed
__device__ __align__(16) ull g_Bf1[27 * 2 * 2 * 32];
__device__ __align__(16) ull g_Bf2[27 * 4 * 2 * 32];
__device__ float g_part[864 * 32];

// ---------------- helpers ----------------
__device__ __forceinline__ int wrapi(int a) {
    return a < 0 ? a + L : (a >= L ? a - L : a);
}
__device__ __forceinline__ float eluf(float x) {
    return x > 0.f ? x : expm1f(x);
}
__device__ __forceinline__ ull pack2ch(float v0, float v1) {
    __nv_bfloat16 h0 = __float2bfloat16(v0);
    __nv_bfloat16 h1 = __float2bfloat16(v1);
    __nv_bfloat16 l0 = __float2bfloat16(v0 - __bfloat162float(h0));
    __nv_bfloat16 l1 = __float2bfloat16(v1 - __bfloat162float(h1));
    uint32_t hu = (uint32_t)__bfloat16_as_ushort(h0) |
                  ((uint32_t)__bfloat16_as_ushort(h1) << 16);
    uint32_t lu = (uint32_t)__bfloat16_as_ushort(l0) |
                  ((uint32_t)__bfloat16_as_ushort(l1) << 16);
    return (ull)hu | ((ull)lu << 32);
}

#define MMA_BF16(D, A, B0, B1)                                              \
    asm("mma.sync.aligned.m16n8k16.row.col.f32.bf16.bf16.f32 "              \
        "{%0,%1,%2,%3}, {%4,%5,%6,%7}, {%8,%9}, {%0,%1,%2,%3};"             \
        : "+f"((D)[0]), "+f"((D)[1]), "+f"((D)[2]), "+f"((D)[3])            \
        : "r"((A)[0]), "r"((A)[1]), "r"((A)[2]), "r"((A)[3]),               \
          "r"(B0), "r"(B1))

// ---------------- Kernel 1: bonds -> packed hi/lo with z-halo ----------------
__global__ __launch_bounds__(256) void bonds_kernel(const int* __restrict__ lx,
                                                    const float* __restrict__ tet) {
    int idx = blockIdx.x * 256 + threadIdx.x;
    if (idx >= L3) return;
    int z = idx % L;
    int y = (idx / L) % L;
    int x = idx / LL2;

    float t00 = tet[0], t01 = tet[1], t10 = tet[2], t11 = tet[3];
    float d00 = t00 * t00 + t01 * t01;
    float d01 = t00 * t10 + t01 * t11;
    float d11 = t10 * t10 + t11 * t11;
    float dt[4] = {d00, d01, d01, d11};

    int4 a = *(const int4*)&lx[idx * 4];
    int a0 = a.x, a1 = a.y, a2 = a.z, a3 = a.w;
    int xm = x ? x - 1 : L - 1;
    int ym = y ? y - 1 : L - 1;
    int zm = z ? z - 1 : L - 1;
    int b1 = lx[((xm * L + y) * L + z) * 4 + 1];
    int b2 = lx[((x * L + ym) * L + z) * 4 + 2];
    int b3 = lx[((x * L + y) * L + zm) * 4 + 3];

    float v[12];
    v[0] = dt[a0 * 2 + a1];  v[1] = dt[a0 * 2 + a2];  v[2]  = dt[a0 * 2 + a3];
    v[3] = dt[a0 * 2 + b1];  v[4] = dt[a0 * 2 + b2];  v[5]  = dt[a0 * 2 + b3];
    v[6] = dt[a1 * 2 + a2];  v[7] = dt[a2 * 2 + a3];  v[8]  = dt[a3 * 2 + a1];
    v[9] = dt[b1 * 2 + b2];  v[10] = dt[b2 * 2 + b3]; v[11] = dt[b3 * 2 + b1];

    ull w[8];
#pragma unroll
    for (int c = 0; c < 6; c++) w[c] = pack2ch(v[2 * c], v[2 * c + 1]);
    w[6] = 0ull; w[7] = 0ull;

    size_t rb = (size_t)(x * L + y) * ROWW;
    ull* dst = &g_bp[rb + (size_t)(z + 1) * 8];
#pragma unroll
    for (int c = 0; c < 8; c++) dst[c] = w[c];
    if (z == 0) {
        ull* d2 = &g_bp[rb + 97 * 8];
#pragma unroll
        for (int c = 0; c < 8; c++) d2[c] = w[c];
    }
    if (z == L - 1) {
        ull* d2 = &g_bp[rb];
#pragma unroll
        for (int c = 0; c < 8; c++) d2[c] = w[c];
    }
}

// ---------------- Kernel 2: weight -> B-fragment prep ----------------
__global__ __launch_bounds__(256) void prep_kernel(const float* __restrict__ w1,
                                                   const float* __restrict__ w2) {
    int i = blockIdx.x * 256 + threadIdx.x;
    if (i < 27 * 2 * 2 * 32) {
        int lane = i & 31, reg = (i >> 5) & 1, nt = (i >> 6) & 1, tap = i >> 7;
        int t = lane & 3;
        int n = nt * 8 + (lane >> 2);
        int k0 = t * 2 + reg * 8;
        float v0 = (k0 < 12)     ? w1[(tap * 12 + k0) * 16 + n]     : 0.f;
        float v1 = (k0 + 1 < 12) ? w1[(tap * 12 + k0 + 1) * 16 + n] : 0.f;
        g_Bf1[i] = pack2ch(v0, v1);
    }
    int j = i - 27 * 2 * 2 * 32;
    if (j >= 0 && j < 27 * 4 * 2 * 32) {
        int lane = j & 31, reg = (j >> 5) & 1, nt = (j >> 6) & 3, tap = j >> 8;
        int t = lane & 3;
        int n = nt * 8 + (lane >> 2);
        int k0 = t * 2 + reg * 8;
        float v0 = w2[(tap * 16 + k0) * 32 + n];
        float v1 = w2[(tap * 16 + k0 + 1) * 32 + n];
        g_Bf2[j] = pack2ch(v0, v1);
    }
}

// ---------------- conv kernels: mma.sync, base+immediate A loads ----------------
// Warp tile = 32 z-consecutive sites. 8 warps/CTA, 4 tiles/warp, 864 CTAs.
template <int NT, bool FIRST>
__global__ __launch_bounds__(256, 2) void conv_kernel(const float* __restrict__ bias) {
    extern __shared__ ull sB[];
    __shared__ float red[8][32];

    const int tid = threadIdx.x;
    const int wid = tid >> 5, lane = tid & 31;
    const int t = lane & 3, r = lane >> 2;

    const ull* Bsrc = FIRST ? g_Bf1 : g_Bf2;
    const int nB = 27 * NT * 2 * 32;
    for (int i = tid; i < nB; i += 256) sB[i] = __ldg(Bsrc + i);
    __syncthreads();

    const ull* Ain = FIRST ? g_bp : g_y1p;
    const int wg = blockIdx.x * 8 + wid;

    float bb0[NT], bb1[NT];
#pragma unroll
    for (int nt = 0; nt < NT; nt++) {
        bb0[nt] = __ldg(bias + nt * 8 + t * 2);
        bb1[nt] = __ldg(bias + nt * 8 + t * 2 + 1);
    }

    float psum0[NT], psum1[NT];
#pragma unroll
    for (int nt = 0; nt < NT; nt++) { psum0[nt] = 0.f; psum1[nt] = 0.f; }

    for (int it = 0; it < 4; it++) {
        int tile = wg * 4 + it;
        int tz = tile % 3;
        int ty = (tile / 3) % L;
        int tx = tile / (3 * L);
        int z0 = tz * 32;
        const int laneoff = (z0 + r) * 8 + t;

        int xs[3], ys[3];
#pragma unroll
        for (int k = 0; k < 3; k++) {
            xs[k] = wrapi(tx + k - 1);
            ys[k] = wrapi(ty + k - 1);
        }

        float d[2][NT][4];
#pragma unroll
        for (int nt = 0; nt < NT; nt++) {
            d[0][nt][0] = bb0[nt]; d[0][nt][1] = bb1[nt];
            d[0][nt][2] = bb0[nt]; d[0][nt][3] = bb1[nt];
            d[1][nt][0] = bb0[nt]; d[1][nt][1] = bb1[nt];
            d[1][nt][2] = bb0[nt]; d[1][nt][3] = bb1[nt];
        }

#pragma unroll
        for (int kd = 0; kd < 3; kd++) {
#pragma unroll
            for (int kh = 0; kh < 3; kh++) {
                // single base pointer; all 24 loads are [R + imm]
                const ull* rp = Ain + (size_t)((xs[kd] * L + ys[kh]) * ROWW + laneoff);
                ull qa[3][4], qb[3][4];
#pragma unroll
                for (int kw = 0; kw < 3; kw++)
#pragma unroll
                    for (int jj = 0; jj < 4; jj++) {
                        qa[kw][jj] = __ldg(rp + kw * 8 + jj * 64);
                        qb[kw][jj] = __ldg(rp + kw * 8 + jj * 64 + 4);
                    }
#pragma unroll
                for (int kw = 0; kw < 3; kw++) {
                    const int tap = (kd * 3 + kh) * 3 + kw;
                    const ull* bp = sB + tap * NT * 64 + lane;
                    uint32_t ah[2][4], al[2][4];
#pragma unroll
                    for (int mt = 0; mt < 2; mt++) {
                        ah[mt][0] = (uint32_t)qa[kw][mt * 2];
                        al[mt][0] = (uint32_t)(qa[kw][mt * 2] >> 32);
                        ah[mt][1] = (uint32_t)qa[kw][mt * 2 + 1];
                        al[mt][1] = (uint32_t)(qa[kw][mt * 2 + 1] >> 32);
                        ah[mt][2] = (uint32_t)qb[kw][mt * 2];
                        al[mt][2] = (uint32_t)(qb[kw][mt * 2] >> 32);
                        ah[mt][3] = (uint32_t)qb[kw][mt * 2 + 1];
                        al[mt][3] = (uint32_t)(qb[kw][mt * 2 + 1] >> 32);
                    }
#pragma unroll
                    for (int nt = 0; nt < NT; nt++) {
                        ull wq0 = bp[nt * 64];
                        ull wq1 = bp[nt * 64 + 32];
                        uint32_t bh0 = (uint32_t)wq0, bl0 = (uint32_t)(wq0 >> 32);
                        uint32_t bh1 = (uint32_t)wq1, bl1 = (uint32_t)(wq1 >> 32);
#pragma unroll
                        for (int mt = 0; mt < 2; mt++) {
                            MMA_BF16(d[mt][nt], ah[mt], bh0, bh1);
                            MMA_BF16(d[mt][nt], ah[mt], bl0, bl1);
                            MMA_BF16(d[mt][nt], al[mt], bh0, bh1);
                        }
                    }
                }
            }
        }

        if (FIRST) {
            // ELU -> packed store with z-halo duplication
            size_t rb = (size_t)(tx * L + ty) * ROWW;
#pragma unroll
            for (int mt = 0; mt < 2; mt++) {
                int za = z0 + mt * 16 + r;       // first row site
                int zb = za + 8;                 // second row site
#pragma unroll
                for (int nt = 0; nt < NT; nt++) {
                    int word = nt * 4 + t;
                    ull va = pack2ch(eluf(d[mt][nt][0]), eluf(d[mt][nt][1]));
                    ull vb = pack2ch(eluf(d[mt][nt][2]), eluf(d[mt][nt][3]));
                    g_y1p[rb + (size_t)(za + 1) * 8 + word] = va;
                    g_y1p[rb + (size_t)(zb + 1) * 8 + word] = vb;
                    if (za == 0)     g_y1p[rb + 97 * 8 + word] = va;
                    if (zb == L - 1) g_y1p[rb + word] = vb;
                }
            }
        } else {
#pragma unroll
            for (int nt = 0; nt < NT; nt++) {
                psum0[nt] += eluf(d[0][nt][0]) + eluf(d[0][nt][2]) +
                             eluf(d[1][nt][0]) + eluf(d[1][nt][2]);
                psum1[nt] += eluf(d[0][nt][1]) + eluf(d[0][nt][3]) +
                             eluf(d[1][nt][1]) + eluf(d[1][nt][3]);
            }
        }
    }

    if (!FIRST) {
        // deterministic reduction over row-slots r (lanes differing in bits 2..4)
#pragma unroll
        for (int off = 4; off <= 16; off <<= 1)
#pragma unroll
            for (int nt = 0; nt < NT; nt++) {
                psum0[nt] += __shfl_xor_sync(0xffffffffu, psum0[nt], off);
                psum1[nt] += __shfl_xor_sync(0xffffffffu, psum1[nt], off);
            }
        if (r == 0) {
#pragma unroll
            for (int nt = 0; nt < NT; nt++) {
                red[wid][nt * 8 + t * 2] = psum0[nt];
                red[wid][nt * 8 + t * 2 + 1] = psum1[nt];
            }
        }
        __syncthreads();
        if (tid < 32) {
            float s = 0.f;
#pragma unroll
            for (int w = 0; w < 8; w++) s += red[w][tid];
            g_part[blockIdx.x * 32 + tid] = s;
        }
    }
}

// ---------------- final reduction (deterministic) ----------------
__global__ __launch_bounds__(256) void final_kernel(const float* __restrict__ wd,
                                                    float* __restrict__ out) {
    __shared__ float sm[256];
    int tt = threadIdx.x, ch = tt & 31, grp = tt >> 5;
    float s = 0.f;
    for (int b = grp; b < 864; b += 8) s += g_part[b * 32 + ch];
    sm[tt] = s;
    __syncthreads();
    if (tt < 32) {
        float v = 0.f;
#pragma unroll
        for (int g = 0; g < 8; g++) v += sm[g * 32 + tt];
        v = (v / (float)L3) * __ldg(wd + tt);
#pragma unroll
        for (int off = 16; off; off >>= 1)
            v += __shfl_xor_sync(0xffffffffu, v, off);
        if (tt == 0) out[0] = v;
    }
}

// ---------------- launch ----------------
extern "C" void kernel_launch(void* const* d_in, const int* in_sizes, int n_in,
                              void* d_out, int out_size) {
    (void)in_sizes; (void)n_in; (void)out_size;
    const int*   lx  = (const int*)d_in[0];
    const float* tet = (const float*)d_in[1];
    const float* w1  = (const float*)d_in[2];
    const float* b1  = (const float*)d_in[3];
    const float* w2  = (const float*)d_in[4];
    const float* b2  = (const float*)d_in[5];
    const float* wd  = (const float*)d_in[6];

    const int SMEM1 = 27 * 2 * 2 * 32 * 8;  // 27648 B
    const int SMEM2 = 27 * 4 * 2 * 32 * 8;  // 55296 B
    cudaFuncSetAttribute(conv_kernel<2, true>,
                         cudaFuncAttributeMaxDynamicSharedMemorySize, SMEM1);
    cudaFuncSetAttribute(conv_kernel<4, false>,
                         cudaFuncAttributeMaxDynamicSharedMemorySize, SMEM2);

    bonds_kernel<<<3456, 256>>>(lx, tet);
    prep_kernel<<<41, 256>>>(w1, w2);
    conv_kernel<2, true><<<864, 256, SMEM1>>>(b1);
    conv_kernel<4, false><<<864, 256, SMEM2>>>(b2);
    final_kernel<<<1, 256>>>(wd, (float*)d_out);
}

// round 6
// speedup vs baseline: 2.4025x; 1.3629x over previous
#include <cuda_runtime.h>
#include <cuda_bf16.h>
#include <cuda_fp16.h>
#include <stdint.h>
#include <math.h>

#define L 96
#define LL2 (L*L)
#define L3 (L*L*L)
#define ZP 98                 // z halo: zp=0 <-> z=95, zp=1..96 <-> z=0..95, zp=97 <-> z=0

typedef unsigned long long ull;

// ---------------- device scratch (allocation-free rule) ----------------
// bonds: per site 4 uint4 (t=0..3): {x=bf16hi pair ch(2t,2t+1), y=bf16lo pair,
//                                    z=bf16hi pair ch(2t+8,2t+9), w=bf16lo pair}
__device__ __align__(16) uint4 g_bp[L * L * ZP * 4];
// y1: per site 4 u64 (t=0..3): {lo32=fp16 pair ch(2t,2t+1), hi32=fp16 pair ch(2t+8,2t+9)}
__device__ __align__(16) ull g_y1p[L * L * ZP * 4];
// B fragments: [tap][nt][reg][lane]; Bf1 bf16 {hi|lo}, Bf2 fp16 {hi|lo}
__device__ __align__(16) ull g_Bf1[27 * 2 * 2 * 32];
__device__ __align__(16) ull g_Bf2[27 * 4 * 2 * 32];
__device__ float g_part[864 * 32];

// ---------------- helpers ----------------
__device__ __forceinline__ int wrapi(int a) {
    return a < 0 ? a + L : (a >= L ? a - L : a);
}
__device__ __forceinline__ float eluf(float x) {
    return x > 0.f ? x : expm1f(x);
}
__device__ __forceinline__ void split2bf(float v0, float v1, uint32_t& hi, uint32_t& lo) {
    __nv_bfloat16 h0 = __float2bfloat16(v0);
    __nv_bfloat16 h1 = __float2bfloat16(v1);
    __nv_bfloat16 l0 = __float2bfloat16(v0 - __bfloat162float(h0));
    __nv_bfloat16 l1 = __float2bfloat16(v1 - __bfloat162float(h1));
    hi = (uint32_t)__bfloat16_as_ushort(h0) | ((uint32_t)__bfloat16_as_ushort(h1) << 16);
    lo = (uint32_t)__bfloat16_as_ushort(l0) | ((uint32_t)__bfloat16_as_ushort(l1) << 16);
}
__device__ __forceinline__ uint32_t h2pack(float a, float b) {
    __half2 h = __floats2half2_rn(a, b);
    return *(uint32_t*)&h;
}

#define MMA_BF16(D, A0, A1, A2, A3, B0, B1)                                 \
    asm("mma.sync.aligned.m16n8k16.row.col.f32.bf16.bf16.f32 "              \
        "{%0,%1,%2,%3}, {%4,%5,%6,%7}, {%8,%9}, {%0,%1,%2,%3};"             \
        : "+f"((D)[0]), "+f"((D)[1]), "+f"((D)[2]), "+f"((D)[3])            \
        : "r"(A0), "r"(A1), "r"(A2), "r"(A3), "r"(B0), "r"(B1))

#define MMA_F16(D, A0, A1, A2, A3, B0, B1)                                  \
    asm("mma.sync.aligned.m16n8k16.row.col.f32.f16.f16.f32 "                \
        "{%0,%1,%2,%3}, {%4,%5,%6,%7}, {%8,%9}, {%0,%1,%2,%3};"             \
        : "+f"((D)[0]), "+f"((D)[1]), "+f"((D)[2]), "+f"((D)[3])            \
        : "r"(A0), "r"(A1), "r"(A2), "r"(A3), "r"(B0), "r"(B1))

// ---------------- Kernel 1: bonds -> bf16 hi/lo uint4, z-halo ----------------
__global__ __launch_bounds__(256) void bonds_kernel(const int* __restrict__ lx,
                                                    const float* __restrict__ tet) {
    int idx = blockIdx.x * 256 + threadIdx.x;
    if (idx >= L3) return;
    int z = idx % L;
    int y = (idx / L) % L;
    int x = idx / LL2;

    float t00 = tet[0], t01 = tet[1], t10 = tet[2], t11 = tet[3];
    float d00 = t00 * t00 + t01 * t01;
    float d01 = t00 * t10 + t01 * t11;
    float d11 = t10 * t10 + t11 * t11;
    float dt[4] = {d00, d01, d01, d11};

    int4 a = *(const int4*)&lx[idx * 4];
    int a0 = a.x, a1 = a.y, a2 = a.z, a3 = a.w;
    int xm = x ? x - 1 : L - 1;
    int ym = y ? y - 1 : L - 1;
    int zm = z ? z - 1 : L - 1;
    int b1 = lx[((xm * L + y) * L + z) * 4 + 1];
    int b2 = lx[((x * L + ym) * L + z) * 4 + 2];
    int b3 = lx[((x * L + y) * L + zm) * 4 + 3];

    float v[16];
    v[0] = dt[a0 * 2 + a1];  v[1] = dt[a0 * 2 + a2];  v[2]  = dt[a0 * 2 + a3];
    v[3] = dt[a0 * 2 + b1];  v[4] = dt[a0 * 2 + b2];  v[5]  = dt[a0 * 2 + b3];
    v[6] = dt[a1 * 2 + a2];  v[7] = dt[a2 * 2 + a3];  v[8]  = dt[a3 * 2 + a1];
    v[9] = dt[b1 * 2 + b2];  v[10] = dt[b2 * 2 + b3]; v[11] = dt[b3 * 2 + b1];
    v[12] = v[13] = v[14] = v[15] = 0.f;

    uint4 q[4];
#pragma unroll
    for (int t = 0; t < 4; t++) {
        split2bf(v[2 * t], v[2 * t + 1], q[t].x, q[t].y);
        split2bf(v[2 * t + 8], v[2 * t + 9], q[t].z, q[t].w);
    }

    size_t rb = (size_t)(x * L + y) * (ZP * 4);
    uint4* dst = &g_bp[rb + (size_t)(z + 1) * 4];
#pragma unroll
    for (int t = 0; t < 4; t++) dst[t] = q[t];
    if (z == 0) {
        uint4* d2 = &g_bp[rb + 97 * 4];
#pragma unroll
        for (int t = 0; t < 4; t++) d2[t] = q[t];
    }
    if (z == L - 1) {
        uint4* d2 = &g_bp[rb];
#pragma unroll
        for (int t = 0; t < 4; t++) d2[t] = q[t];
    }
}

// ---------------- Kernel 2: weight -> B-fragment prep ----------------
__global__ __launch_bounds__(256) void prep_kernel(const float* __restrict__ w1,
                                                   const float* __restrict__ w2) {
    int i = blockIdx.x * 256 + threadIdx.x;
    if (i < 27 * 2 * 2 * 32) {  // conv1: bf16 hi|lo
        int lane = i & 31, reg = (i >> 5) & 1, nt = (i >> 6) & 1, tap = i >> 7;
        int t = lane & 3;
        int n = nt * 8 + (lane >> 2);
        int k0 = t * 2 + reg * 8;
        float v0 = (k0 < 12)     ? w1[(tap * 12 + k0) * 16 + n]     : 0.f;
        float v1 = (k0 + 1 < 12) ? w1[(tap * 12 + k0 + 1) * 16 + n] : 0.f;
        uint32_t hi, lo;
        split2bf(v0, v1, hi, lo);
        g_Bf1[i] = (ull)hi | ((ull)lo << 32);
    }
    int j = i - 27 * 2 * 2 * 32;
    if (j >= 0 && j < 27 * 4 * 2 * 32) {  // conv2: fp16 hi|lo
        int lane = j & 31, reg = (j >> 5) & 1, nt = (j >> 6) & 3, tap = j >> 8;
        int t = lane & 3;
        int n = nt * 8 + (lane >> 2);
        int k0 = t * 2 + reg * 8;
        float v0 = w2[(tap * 16 + k0) * 32 + n];
        float v1 = w2[(tap * 16 + k0 + 1) * 32 + n];
        __half h0 = __float2half_rn(v0), h1 = __float2half_rn(v1);
        __half l0 = __float2half_rn(v0 - __half2float(h0));
        __half l1 = __float2half_rn(v1 - __half2float(h1));
        uint32_t hu = (uint32_t)__half_as_ushort(h0) | ((uint32_t)__half_as_ushort(h1) << 16);
        uint32_t lu = (uint32_t)__half_as_ushort(l0) | ((uint32_t)__half_as_ushort(l1) << 16);
        g_Bf2[j] = (ull)hu | ((ull)lu << 32);
    }
}

// ---------------- conv1: bf16 3-term, LDG.128 A path ----------------
// Warp tile = 32 z-consecutive sites. 8 warps/CTA, 4 tiles/warp, 864 CTAs.
__global__ __launch_bounds__(256, 2) void conv1_kernel(const float* __restrict__ bias) {
    extern __shared__ ull sB[];
    const int tid = threadIdx.x;
    const int wid = tid >> 5, lane = tid & 31;
    const int t = lane & 3, r = lane >> 2;

    for (int i = tid; i < 27 * 2 * 2 * 32; i += 256) sB[i] = __ldg(g_Bf1 + i);
    __syncthreads();

    const int wg = blockIdx.x * 8 + wid;
    float bb0[2], bb1[2];
#pragma unroll
    for (int nt = 0; nt < 2; nt++) {
        bb0[nt] = __ldg(bias + nt * 8 + t * 2);
        bb1[nt] = __ldg(bias + nt * 8 + t * 2 + 1);
    }

    for (int it = 0; it < 4; it++) {
        int tile = wg * 4 + it;
        int tz = tile % 3;
        int ty = (tile / 3) % L;
        int tx = tile / (3 * L);
        int z0 = tz * 32;
        const int laneoff = (z0 + r) * 4 + t;

        int xs[3], ys[3];
#pragma unroll
        for (int k = 0; k < 3; k++) { xs[k] = wrapi(tx + k - 1); ys[k] = wrapi(ty + k - 1); }

        float d[2][2][4];
#pragma unroll
        for (int nt = 0; nt < 2; nt++) {
            d[0][nt][0] = bb0[nt]; d[0][nt][1] = bb1[nt];
            d[0][nt][2] = bb0[nt]; d[0][nt][3] = bb1[nt];
            d[1][nt][0] = bb0[nt]; d[1][nt][1] = bb1[nt];
            d[1][nt][2] = bb0[nt]; d[1][nt][3] = bb1[nt];
        }

#pragma unroll
        for (int kd = 0; kd < 3; kd++) {
#pragma unroll
            for (int kh = 0; kh < 3; kh++) {
                const uint4* rp = g_bp + (size_t)((xs[kd] * L + ys[kh]) * (ZP * 4) + laneoff);
                uint4 q[3][4];
#pragma unroll
                for (int kw = 0; kw < 3; kw++)
#pragma unroll
                    for (int jj = 0; jj < 4; jj++)
                        q[kw][jj] = __ldg(rp + kw * 4 + jj * 32);
#pragma unroll
                for (int kw = 0; kw < 3; kw++) {
                    const int tap = (kd * 3 + kh) * 3 + kw;
                    const ull* bp = sB + tap * 128 + lane;
#pragma unroll
                    for (int nt = 0; nt < 2; nt++) {
                        ull wq0 = bp[nt * 64];
                        ull wq1 = bp[nt * 64 + 32];
                        uint32_t bh0 = (uint32_t)wq0, bl0 = (uint32_t)(wq0 >> 32);
                        uint32_t bh1 = (uint32_t)wq1, bl1 = (uint32_t)(wq1 >> 32);
#pragma unroll
                        for (int mt = 0; mt < 2; mt++) {
                            const uint4& za = q[kw][mt * 2];
                            const uint4& zb = q[kw][mt * 2 + 1];
                            MMA_BF16(d[mt][nt], za.x, zb.x, za.z, zb.z, bh0, bh1);
                            MMA_BF16(d[mt][nt], za.x, zb.x, za.z, zb.z, bl0, bl1);
                            MMA_BF16(d[mt][nt], za.y, zb.y, za.w, zb.w, bh0, bh1);
                        }
                    }
                }
            }
        }

        // ELU -> fp16 single-plane store (word t = {nt0 pair | nt1 pair}), z-halo dup
        size_t rb = (size_t)(tx * L + ty) * (ZP * 4);
#pragma unroll
        for (int mt = 0; mt < 2; mt++) {
            int za = z0 + mt * 16 + r;
            int zb = za + 8;
            ull va = (ull)h2pack(eluf(d[mt][0][0]), eluf(d[mt][0][1])) |
                     ((ull)h2pack(eluf(d[mt][1][0]), eluf(d[mt][1][1])) << 32);
            ull vb = (ull)h2pack(eluf(d[mt][0][2]), eluf(d[mt][0][3])) |
                     ((ull)h2pack(eluf(d[mt][1][2]), eluf(d[mt][1][3])) << 32);
            g_y1p[rb + (size_t)(za + 1) * 4 + t] = va;
            g_y1p[rb + (size_t)(zb + 1) * 4 + t] = vb;
            if (za == 0)     g_y1p[rb + 97 * 4 + t] = va;
            if (zb == L - 1) g_y1p[rb + t] = vb;
        }
    }
}

// ---------------- conv2: fp16 2-term (A single plane, B hi+lo) ----------------
__global__ __launch_bounds__(256, 2) void conv2_kernel(const float* __restrict__ bias) {
    extern __shared__ ull sB[];
    __shared__ float red[8][32];

    const int tid = threadIdx.x;
    const int wid = tid >> 5, lane = tid & 31;
    const int t = lane & 3, r = lane >> 2;

    for (int i = tid; i < 27 * 4 * 2 * 32; i += 256) sB[i] = __ldg(g_Bf2 + i);
    __syncthreads();

    const int wg = blockIdx.x * 8 + wid;
    float bb0[4], bb1[4];
#pragma unroll
    for (int nt = 0; nt < 4; nt++) {
        bb0[nt] = __ldg(bias + nt * 8 + t * 2);
        bb1[nt] = __ldg(bias + nt * 8 + t * 2 + 1);
    }

    float psum0[4], psum1[4];
#pragma unroll
    for (int nt = 0; nt < 4; nt++) { psum0[nt] = 0.f; psum1[nt] = 0.f; }

    for (int it = 0; it < 4; it++) {
        int tile = wg * 4 + it;
        int tz = tile % 3;
        int ty = (tile / 3) % L;
        int tx = tile / (3 * L);
        int z0 = tz * 32;
        const int laneoff = (z0 + r) * 4 + t;

        int xs[3], ys[3];
#pragma unroll
        for (int k = 0; k < 3; k++) { xs[k] = wrapi(tx + k - 1); ys[k] = wrapi(ty + k - 1); }

        float d[2][4][4];
#pragma unroll
        for (int nt = 0; nt < 4; nt++) {
            d[0][nt][0] = bb0[nt]; d[0][nt][1] = bb1[nt];
            d[0][nt][2] = bb0[nt]; d[0][nt][3] = bb1[nt];
            d[1][nt][0] = bb0[nt]; d[1][nt][1] = bb1[nt];
            d[1][nt][2] = bb0[nt]; d[1][nt][3] = bb1[nt];
        }

#pragma unroll
        for (int kd = 0; kd < 3; kd++) {
#pragma unroll
            for (int kh = 0; kh < 3; kh++) {
                const ull* rp = g_y1p + (size_t)((xs[kd] * L + ys[kh]) * (ZP * 4) + laneoff);
                ull q[3][4];
#pragma unroll
                for (int kw = 0; kw < 3; kw++)
#pragma unroll
                    for (int jj = 0; jj < 4; jj++)
                        q[kw][jj] = __ldg(rp + kw * 4 + jj * 32);
#pragma unroll
                for (int kw = 0; kw < 3; kw++) {
                    const int tap = (kd * 3 + kh) * 3 + kw;
                    const ull* bp = sB + tap * 256 + lane;
                    uint32_t a0[2], a1[2], a2[2], a3[2];
#pragma unroll
                    for (int mt = 0; mt < 2; mt++) {
                        a0[mt] = (uint32_t)q[kw][mt * 2];
                        a1[mt] = (uint32_t)q[kw][mt * 2 + 1];
                        a2[mt] = (uint32_t)(q[kw][mt * 2] >> 32);
                        a3[mt] = (uint32_t)(q[kw][mt * 2 + 1] >> 32);
                    }
#pragma unroll
                    for (int nt = 0; nt < 4; nt++) {
                        ull wq0 = bp[nt * 64];
                        ull wq1 = bp[nt * 64 + 32];
                        uint32_t bh0 = (uint32_t)wq0, bl0 = (uint32_t)(wq0 >> 32);
                        uint32_t bh1 = (uint32_t)wq1, bl1 = (uint32_t)(wq1 >> 32);
#pragma unroll
                        for (int mt = 0; mt < 2; mt++) {
                            MMA_F16(d[mt][nt], a0[mt], a1[mt], a2[mt], a3[mt], bh0, bh1);
                            MMA_F16(d[mt][nt], a0[mt], a1[mt], a2[mt], a3[mt], bl0, bl1);
                        }
                    }
                }
            }
        }

#pragma unroll
        for (int nt = 0; nt < 4; nt++) {
            psum0[nt] += eluf(d[0][nt][0]) + eluf(d[0][nt][2]) +
                         eluf(d[1][nt][0]) + eluf(d[1][nt][2]);
            psum1[nt] += eluf(d[0][nt][1]) + eluf(d[0][nt][3]) +
                         eluf(d[1][nt][1]) + eluf(d[1][nt][3]);
        }
    }

    // deterministic reduction over row-slots r (lane bits 2..4)
#pragma unroll
    for (int off = 4; off <= 16; off <<= 1)
#pragma unroll
        for (int nt = 0; nt < 4; nt++) {
            psum0[nt] += __shfl_xor_sync(0xffffffffu, psum0[nt], off);
            psum1[nt] += __shfl_xor_sync(0xffffffffu, psum1[nt], off);
        }
    if (r == 0) {
#pragma unroll
        for (int nt = 0; nt < 4; nt++) {
            red[wid][nt * 8 + t * 2] = psum0[nt];
            red[wid][nt * 8 + t * 2 + 1] = psum1[nt];
        }
    }
    __syncthreads();
    if (tid < 32) {
        float s = 0.f;
#pragma unroll
        for (int w = 0; w < 8; w++) s += red[w][tid];
        g_part[blockIdx.x * 32 + tid] = s;
    }
}

// ---------------- final reduction (deterministic) ----------------
__global__ __launch_bounds__(256) void final_kernel(const float* __restrict__ wd,
                                                    float* __restrict__ out) {
    __shared__ float sm[256];
    int tt = threadIdx.x, ch = tt & 31, grp = tt >> 5;
    float s = 0.f;
    for (int b = grp; b < 864; b += 8) s += g_part[b * 32 + ch];
    sm[tt] = s;
    __syncthreads();
    if (tt < 32) {
        float v = 0.f;
#pragma unroll
        for (int g = 0; g < 8; g++) v += sm[g * 32 + tt];
        v = (v / (float)L3) * __ldg(wd + tt);
#pragma unroll
        for (int off = 16; off; off >>= 1)
            v += __shfl_xor_sync(0xffffffffu, v, off);
        if (tt == 0) out[0] = v;
    }
}

// ---------------- launch ----------------
extern "C" void kernel_launch(void* const* d_in, const int* in_sizes, int n_in,
                              void* d_out, int out_size) {
    (void)in_sizes; (void)n_in; (void)out_size;
    const int*   lx  = (const int*)d_in[0];
    const float* tet = (const float*)d_in[1];
    const float* w1  = (const float*)d_in[2];
    const float* b1  = (const float*)d_in[3];
    const float* w2  = (const float*)d_in[4];
    const float* b2  = (const float*)d_in[5];
    const float* wd  = (const float*)d_in[6];

    const int SMEM1 = 27 * 2 * 2 * 32 * 8;  // 27648 B
    const int SMEM2 = 27 * 4 * 2 * 32 * 8;  // 55296 B
    cudaFuncSetAttribute(conv1_kernel,
                         cudaFuncAttributeMaxDynamicSharedMemorySize, SMEM1);
    cudaFuncSetAttribute(conv2_kernel,
                         cudaFuncAttributeMaxDynamicSharedMemorySize, SMEM2);

    bonds_kernel<<<3456, 256>>>(lx, tet);
    prep_kernel<<<41, 256>>>(w1, w2);
    conv1_kernel<<<864, 256, SMEM1>>>(b1);
    conv2_kernel<<<864, 256, SMEM2>>>(b2);
    final_kernel<<<1, 256>>>(wd, (float*)d_out);
}

// round 7
// speedup vs baseline: 2.9838x; 1.2420x over previous
#include <cuda_runtime.h>
#include <cuda_bf16.h>
#include <cuda_fp16.h>
#include <stdint.h>
#include <math.h>

#define L 96
#define LL2 (L*L)
#define L3 (L*L*L)
#define ZP 98                 // z halo: zp=0 <-> z=95, zp=1..96 <-> z=0..95, zp=97 <-> z=0

typedef unsigned long long ull;

// ---------------- device scratch (allocation-free rule) ----------------
// bonds: per site 4 uint4 (t=0..3): {x=bf16hi pair ch(2t,2t+1), y=bf16lo pair,
//                                    z=bf16hi pair ch(2t+8,2t+9), w=bf16lo pair}
__device__ __align__(16) uint4 g_bp[L * L * ZP * 4];
// y1: per site 4 u64 (t=0..3): {lo32=fp16 pair ch(2t,2t+1), hi32=fp16 pair ch(2t+8,2t+9)}
__device__ __align__(16) ull g_y1p[L * L * ZP * 4];
// B fragments as uint4 {bh0,bh1,bl0,bl1} per (tap,nt,lane)
__device__ __align__(16) uint4 g_Bf1[27 * 2 * 32];   // conv1, bf16
__device__ __align__(16) uint4 g_Bf2[27 * 4 * 32];   // conv2, fp16
__device__ float g_part[864 * 32];

// ---------------- helpers ----------------
__device__ __forceinline__ int wrapi(int a) {
    return a < 0 ? a + L : (a >= L ? a - L : a);
}
__device__ __forceinline__ float eluf(float x) {
    return x > 0.f ? x : (__expf(x) - 1.f);   // MUFU-based, ~3 instr
}
__device__ __forceinline__ void split2bf(float v0, float v1, uint32_t& hi, uint32_t& lo) {
    __nv_bfloat16 h0 = __float2bfloat16(v0);
    __nv_bfloat16 h1 = __float2bfloat16(v1);
    __nv_bfloat16 l0 = __float2bfloat16(v0 - __bfloat162float(h0));
    __nv_bfloat16 l1 = __float2bfloat16(v1 - __bfloat162float(h1));
    hi = (uint32_t)__bfloat16_as_ushort(h0) | ((uint32_t)__bfloat16_as_ushort(h1) << 16);
    lo = (uint32_t)__bfloat16_as_ushort(l0) | ((uint32_t)__bfloat16_as_ushort(l1) << 16);
}
__device__ __forceinline__ void split2h(float v0, float v1, uint32_t& hi, uint32_t& lo) {
    __half h0 = __float2half_rn(v0), h1 = __float2half_rn(v1);
    __half l0 = __float2half_rn(v0 - __half2float(h0));
    __half l1 = __float2half_rn(v1 - __half2float(h1));
    hi = (uint32_t)__half_as_ushort(h0) | ((uint32_t)__half_as_ushort(h1) << 16);
    lo = (uint32_t)__half_as_ushort(l0) | ((uint32_t)__half_as_ushort(l1) << 16);
}
__device__ __forceinline__ uint32_t h2pack(float a, float b) {
    __half2 h = __floats2half2_rn(a, b);
    return *(uint32_t*)&h;
}

#define MMA_BF16(D, A0, A1, A2, A3, B0, B1)                                 \
    asm("mma.sync.aligned.m16n8k16.row.col.f32.bf16.bf16.f32 "              \
        "{%0,%1,%2,%3}, {%4,%5,%6,%7}, {%8,%9}, {%0,%1,%2,%3};"             \
        : "+f"((D)[0]), "+f"((D)[1]), "+f"((D)[2]), "+f"((D)[3])            \
        : "r"(A0), "r"(A1), "r"(A2), "r"(A3), "r"(B0), "r"(B1))

#define MMA_F16(D, A0, A1, A2, A3, B0, B1)                                  \
    asm("mma.sync.aligned.m16n8k16.row.col.f32.f16.f16.f32 "                \
        "{%0,%1,%2,%3}, {%4,%5,%6,%7}, {%8,%9}, {%0,%1,%2,%3};"             \
        : "+f"((D)[0]), "+f"((D)[1]), "+f"((D)[2]), "+f"((D)[3])            \
        : "r"(A0), "r"(A1), "r"(A2), "r"(A3), "r"(B0), "r"(B1))

// ---------------- Kernel 1: bonds -> bf16 hi/lo uint4, z-halo ----------------
__global__ __launch_bounds__(256) void bonds_kernel(const int* __restrict__ lx,
                                                    const float* __restrict__ tet) {
    int idx = blockIdx.x * 256 + threadIdx.x;
    if (idx >= L3) return;
    int z = idx % L;
    int y = (idx / L) % L;
    int x = idx / LL2;

    float t00 = tet[0], t01 = tet[1], t10 = tet[2], t11 = tet[3];
    float d00 = t00 * t00 + t01 * t01;
    float d01 = t00 * t10 + t01 * t11;
    float d11 = t10 * t10 + t11 * t11;
    float dt[4] = {d00, d01, d01, d11};

    int4 a = *(const int4*)&lx[idx * 4];
    int a0 = a.x, a1 = a.y, a2 = a.z, a3 = a.w;
    int xm = x ? x - 1 : L - 1;
    int ym = y ? y - 1 : L - 1;
    int zm = z ? z - 1 : L - 1;
    int b1 = lx[((xm * L + y) * L + z) * 4 + 1];
    int b2 = lx[((x * L + ym) * L + z) * 4 + 2];
    int b3 = lx[((x * L + y) * L + zm) * 4 + 3];

    float v[16];
    v[0] = dt[a0 * 2 + a1];  v[1] = dt[a0 * 2 + a2];  v[2]  = dt[a0 * 2 + a3];
    v[3] = dt[a0 * 2 + b1];  v[4] = dt[a0 * 2 + b2];  v[5]  = dt[a0 * 2 + b3];
    v[6] = dt[a1 * 2 + a2];  v[7] = dt[a2 * 2 + a3];  v[8]  = dt[a3 * 2 + a1];
    v[9] = dt[b1 * 2 + b2];  v[10] = dt[b2 * 2 + b3]; v[11] = dt[b3 * 2 + b1];
    v[12] = v[13] = v[14] = v[15] = 0.f;

    uint4 q[4];
#pragma unroll
    for (int t = 0; t < 4; t++) {
        split2bf(v[2 * t], v[2 * t + 1], q[t].x, q[t].y);
        split2bf(v[2 * t + 8], v[2 * t + 9], q[t].z, q[t].w);
    }

    size_t rb = (size_t)(x * L + y) * (ZP * 4);
    uint4* dst = &g_bp[rb + (size_t)(z + 1) * 4];
#pragma unroll
    for (int t = 0; t < 4; t++) dst[t] = q[t];
    if (z == 0) {
        uint4* d2 = &g_bp[rb + 97 * 4];
#pragma unroll
        for (int t = 0; t < 4; t++) d2[t] = q[t];
    }
    if (z == L - 1) {
        uint4* d2 = &g_bp[rb];
#pragma unroll
        for (int t = 0; t < 4; t++) d2[t] = q[t];
    }
}

// ---------------- Kernel 2: weight -> B-fragment prep (uint4 layout) ----------------
__global__ __launch_bounds__(256) void prep_kernel(const float* __restrict__ w1,
                                                   const float* __restrict__ w2) {
    int i = blockIdx.x * 256 + threadIdx.x;
    if (i < 27 * 2 * 32) {  // conv1: bf16
        int lane = i & 31, nt = (i >> 5) & 1, tap = i >> 6;
        int t = lane & 3;
        int n = nt * 8 + (lane >> 2);
        int k0 = t * 2;
        float v00 = (k0 < 12)      ? w1[(tap * 12 + k0) * 16 + n]      : 0.f;
        float v01 = (k0 + 1 < 12)  ? w1[(tap * 12 + k0 + 1) * 16 + n]  : 0.f;
        float v10 = (k0 + 8 < 12)  ? w1[(tap * 12 + k0 + 8) * 16 + n]  : 0.f;
        float v11 = (k0 + 9 < 12)  ? w1[(tap * 12 + k0 + 9) * 16 + n]  : 0.f;
        uint4 o;
        split2bf(v00, v01, o.x, o.z);
        split2bf(v10, v11, o.y, o.w);
        g_Bf1[i] = o;
    }
    int j = i - 27 * 2 * 32;
    if (j >= 0 && j < 27 * 4 * 32) {  // conv2: fp16
        int lane = j & 31, nt = (j >> 5) & 3, tap = j >> 7;
        int t = lane & 3;
        int n = nt * 8 + (lane >> 2);
        int k0 = t * 2;
        float v00 = w2[(tap * 16 + k0) * 32 + n];
        float v01 = w2[(tap * 16 + k0 + 1) * 32 + n];
        float v10 = w2[(tap * 16 + k0 + 8) * 32 + n];
        float v11 = w2[(tap * 16 + k0 + 9) * 32 + n];
        uint4 o;
        split2h(v00, v01, o.x, o.z);
        split2h(v10, v11, o.y, o.w);
        g_Bf2[j] = o;
    }
}

// ---------------- conv1: bf16 3-term ----------------
// Warp tile = 32 z-consecutive sites. 8 warps/CTA, 4 tiles/warp, 864 CTAs.
__global__ __launch_bounds__(256, 2) void conv1_kernel(const float* __restrict__ bias) {
    extern __shared__ uint4 sB4[];
    const int tid = threadIdx.x;
    const int wid = tid >> 5, lane = tid & 31;
    const int t = lane & 3, r = lane >> 2;

    for (int i = tid; i < 27 * 2 * 32; i += 256) sB4[i] = __ldg(g_Bf1 + i);
    __syncthreads();

    const int wg = blockIdx.x * 8 + wid;
    float bb0[2], bb1[2];
#pragma unroll
    for (int nt = 0; nt < 2; nt++) {
        bb0[nt] = __ldg(bias + nt * 8 + t * 2);
        bb1[nt] = __ldg(bias + nt * 8 + t * 2 + 1);
    }

    for (int it = 0; it < 4; it++) {
        int tile = wg * 4 + it;
        int tz = tile % 3;
        int ty = (tile / 3) % L;
        int tx = tile / (3 * L);
        int z0 = tz * 32;
        const int laneoff = (z0 + r) * 4 + t;

        int xs[3], ys[3];
#pragma unroll
        for (int k = 0; k < 3; k++) { xs[k] = wrapi(tx + k - 1); ys[k] = wrapi(ty + k - 1); }

        float d[2][2][4];
#pragma unroll
        for (int nt = 0; nt < 2; nt++) {
            d[0][nt][0] = bb0[nt]; d[0][nt][1] = bb1[nt];
            d[0][nt][2] = bb0[nt]; d[0][nt][3] = bb1[nt];
            d[1][nt][0] = bb0[nt]; d[1][nt][1] = bb1[nt];
            d[1][nt][2] = bb0[nt]; d[1][nt][3] = bb1[nt];
        }

#pragma unroll
        for (int kd = 0; kd < 3; kd++) {
#pragma unroll
            for (int kh = 0; kh < 3; kh++) {
                const uint4* rp = g_bp + (size_t)((xs[kd] * L + ys[kh]) * (ZP * 4) + laneoff);
                uint4 q[3][4];
#pragma unroll
                for (int kw = 0; kw < 3; kw++)
#pragma unroll
                    for (int jj = 0; jj < 4; jj++)
                        q[kw][jj] = __ldg(rp + kw * 4 + jj * 32);
#pragma unroll
                for (int kw = 0; kw < 3; kw++) {
                    const int tap = (kd * 3 + kh) * 3 + kw;
#pragma unroll
                    for (int nt = 0; nt < 2; nt++) {
                        uint4 wb = sB4[(tap * 2 + nt) * 32 + lane];  // 1 LDS.128
#pragma unroll
                        for (int mt = 0; mt < 2; mt++) {
                            const uint4& za = q[kw][mt * 2];
                            const uint4& zb = q[kw][mt * 2 + 1];
                            MMA_BF16(d[mt][nt], za.x, zb.x, za.z, zb.z, wb.x, wb.y);
                            MMA_BF16(d[mt][nt], za.x, zb.x, za.z, zb.z, wb.z, wb.w);
                            MMA_BF16(d[mt][nt], za.y, zb.y, za.w, zb.w, wb.x, wb.y);
                        }
                    }
                }
            }
        }

        // ELU -> fp16 single-plane store (word t = {nt0 pair | nt1 pair}), z-halo dup
        size_t rb = (size_t)(tx * L + ty) * (ZP * 4);
#pragma unroll
        for (int mt = 0; mt < 2; mt++) {
            int za = z0 + mt * 16 + r;
            int zb = za + 8;
            ull va = (ull)h2pack(eluf(d[mt][0][0]), eluf(d[mt][0][1])) |
                     ((ull)h2pack(eluf(d[mt][1][0]), eluf(d[mt][1][1])) << 32);
            ull vb = (ull)h2pack(eluf(d[mt][0][2]), eluf(d[mt][0][3])) |
                     ((ull)h2pack(eluf(d[mt][1][2]), eluf(d[mt][1][3])) << 32);
            g_y1p[rb + (size_t)(za + 1) * 4 + t] = va;
            g_y1p[rb + (size_t)(zb + 1) * 4 + t] = vb;
            if (za == 0)     g_y1p[rb + 97 * 4 + t] = va;
            if (zb == L - 1) g_y1p[rb + t] = vb;
        }
    }
}

// ---------------- conv2: fp16 2-term (A single plane, B hi+lo) ----------------
__global__ __launch_bounds__(256, 2) void conv2_kernel(const float* __restrict__ bias) {
    extern __shared__ uint4 sB4[];
    __shared__ float red[8][32];

    const int tid = threadIdx.x;
    const int wid = tid >> 5, lane = tid & 31;
    const int t = lane & 3, r = lane >> 2;

    for (int i = tid; i < 27 * 4 * 32; i += 256) sB4[i] = __ldg(g_Bf2 + i);
    __syncthreads();

    const int wg = blockIdx.x * 8 + wid;
    float bb0[4], bb1[4];
#pragma unroll
    for (int nt = 0; nt < 4; nt++) {
        bb0[nt] = __ldg(bias + nt * 8 + t * 2);
        bb1[nt] = __ldg(bias + nt * 8 + t * 2 + 1);
    }

    float psum0[4], psum1[4];
#pragma unroll
    for (int nt = 0; nt < 4; nt++) { psum0[nt] = 0.f; psum1[nt] = 0.f; }

    for (int it = 0; it < 4; it++) {
        int tile = wg * 4 + it;
        int tz = tile % 3;
        int ty = (tile / 3) % L;
        int tx = tile / (3 * L);
        int z0 = tz * 32;
        const int laneoff = (z0 + r) * 4 + t;

        int xs[3], ys[3];
#pragma unroll
        for (int k = 0; k < 3; k++) { xs[k] = wrapi(tx + k - 1); ys[k] = wrapi(ty + k - 1); }

        float d[2][4][4];
#pragma unroll
        for (int nt = 0; nt < 4; nt++) {
            d[0][nt][0] = bb0[nt]; d[0][nt][1] = bb1[nt];
            d[0][nt][2] = bb0[nt]; d[0][nt][3] = bb1[nt];
            d[1][nt][0] = bb0[nt]; d[1][nt][1] = bb1[nt];
            d[1][nt][2] = bb0[nt]; d[1][nt][3] = bb1[nt];
        }

#pragma unroll
        for (int kd = 0; kd < 3; kd++) {
#pragma unroll
            for (int kh = 0; kh < 3; kh++) {
                const uint2* rp = (const uint2*)g_y1p +
                                  (size_t)((xs[kd] * L + ys[kh]) * (ZP * 4) + laneoff);
                uint2 q[3][4];
#pragma unroll
                for (int kw = 0; kw < 3; kw++)
#pragma unroll
                    for (int jj = 0; jj < 4; jj++)
                        q[kw][jj] = __ldg(rp + kw * 4 + jj * 32);
#pragma unroll
                for (int kw = 0; kw < 3; kw++) {
                    const int tap = (kd * 3 + kh) * 3 + kw;
#pragma unroll
                    for (int nt = 0; nt < 4; nt++) {
                        uint4 wb = sB4[(tap * 4 + nt) * 32 + lane];  // 1 LDS.128
#pragma unroll
                        for (int mt = 0; mt < 2; mt++) {
                            const uint2& za = q[kw][mt * 2];
                            const uint2& zb = q[kw][mt * 2 + 1];
                            MMA_F16(d[mt][nt], za.x, zb.x, za.y, zb.y, wb.x, wb.y);
                            MMA_F16(d[mt][nt], za.x, zb.x, za.y, zb.y, wb.z, wb.w);
                        }
                    }
                }
            }
        }

#pragma unroll
        for (int nt = 0; nt < 4; nt++) {
            psum0[nt] += eluf(d[0][nt][0]) + eluf(d[0][nt][2]) +
                         eluf(d[1][nt][0]) + eluf(d[1][nt][2]);
            psum1[nt] += eluf(d[0][nt][1]) + eluf(d[0][nt][3]) +
                         eluf(d[1][nt][1]) + eluf(d[1][nt][3]);
        }
    }

    // deterministic reduction over row-slots r (lane bits 2..4)
#pragma unroll
    for (int off = 4; off <= 16; off <<= 1)
#pragma unroll
        for (int nt = 0; nt < 4; nt++) {
            psum0[nt] += __shfl_xor_sync(0xffffffffu, psum0[nt], off);
            psum1[nt] += __shfl_xor_sync(0xffffffffu, psum1[nt], off);
        }
    if (r == 0) {
#pragma unroll
        for (int nt = 0; nt < 4; nt++) {
            red[wid][nt * 8 + t * 2] = psum0[nt];
            red[wid][nt * 8 + t * 2 + 1] = psum1[nt];
        }
    }
    __syncthreads();
    if (tid < 32) {
        float s = 0.f;
#pragma unroll
        for (int w = 0; w < 8; w++) s += red[w][tid];
        g_part[blockIdx.x * 32 + tid] = s;
    }
}

// ---------------- final reduction (deterministic) ----------------
__global__ __launch_bounds__(256) void final_kernel(const float* __restrict__ wd,
                                                    float* __restrict__ out) {
    __shared__ float sm[256];
    int tt = threadIdx.x, ch = tt & 31, grp = tt >> 5;
    float s = 0.f;
    for (int b = grp; b < 864; b += 8) s += g_part[b * 32 + ch];
    sm[tt] = s;
    __syncthreads();
    if (tt < 32) {
        float v = 0.f;
#pragma unroll
        for (int g = 0; g < 8; g++) v += sm[g * 32 + tt];
        v = (v / (float)L3) * __ldg(wd + tt);
#pragma unroll
        for (int off = 16; off; off >>= 1)
            v += __shfl_xor_sync(0xffffffffu, v, off);
        if (tt == 0) out[0] = v;
    }
}

// ---------------- launch ----------------
extern "C" void kernel_launch(void* const* d_in, const int* in_sizes, int n_in,
                              void* d_out, int out_size) {
    (void)in_sizes; (void)n_in; (void)out_size;
    const int*   lx  = (const int*)d_in[0];
    const float* tet = (const float*)d_in[1];
    const float* w1  = (const float*)d_in[2];
    const float* b1  = (const float*)d_in[3];
    const float* w2  = (const float*)d_in[4];
    const float* b2  = (const float*)d_in[5];
    const float* wd  = (const float*)d_in[6];

    const int SMEM1 = 27 * 2 * 32 * 16;  // 27648 B
    const int SMEM2 = 27 * 4 * 32 * 16;  // 55296 B
    cudaFuncSetAttribute(conv1_kernel,
                         cudaFuncAttributeMaxDynamicSharedMemorySize, SMEM1);
    cudaFuncSetAttribute(conv2_kernel,
                         cudaFuncAttributeMaxDynamicSharedMemorySize, SMEM2);

    bonds_kernel<<<3456, 256>>>(lx, tet);
    prep_kernel<<<41, 256>>>(w1, w2);
    conv1_kernel<<<864, 256, SMEM1>>>(b1);
    conv2_kernel<<<864, 256, SMEM2>>>(b2);
    final_kernel<<<1, 256>>>(wd, (float*)d_out);
}